// round 17
// baseline (speedup 1.0000x reference)
#include <cuda_runtime.h>

// N = 2^26 FFT of REAL fp32 input via half-length complex FFT (M = 2^25):
//   z[n] = x[2n] + i x[2n+1] (free reinterpret), Z = FFT_M(z), Hermitian unpack.
// UNFUSED schedule:
//   P1: radix-256, s=1        z   -> D    (d_out scratch)   [verified r7-r16]
//   P2: radix-512, s=256      D   -> Blo  (g_buf lo)        [verified r12-r16]
//   P3: radix-256 FINAL, ps=0 Blo -> Bhi  (g_buf hi)        [verified r16]
//   U:  Hermitian unpack, ILP-2 (two independent k per thread) Bhi -> out

#define NFFT  (1u << 26)
#define MFFT  (1u << 25)
#define M256  (1u << 17)   // MFFT/256
#define M512  (1u << 16)   // MFFT/512
#define SFIN  (1u << 17)   // final-pass stride s = M/256
#define MHALF (1u << 24)
#define MQUART (1u << 23)
#define TWO_PI 6.28318530717958647692f
#define INVM  (1.0f / 33554432.0f)
#define INVN  (1.0f / 67108864.0f)

static __device__ float2 g_buf[NFFT];  // 512 MB scratch (sanctioned)

// exp(-2*pi*i*j/256), j = 0..15
__constant__ float2 c_w256[16] = {
    { 1.00000000000000000f, -0.00000000000000000f},
    { 0.99969881869620422f, -0.02454122852291229f},
    { 0.99879545620517241f, -0.04906767432741801f},
    { 0.99729045667869021f, -0.07356456359966743f},
    { 0.99518472667219693f, -0.09801714032956060f},
    { 0.99247953459870997f, -0.12241067519921620f},
    { 0.98917650996478101f, -0.14673047445536175f},
    { 0.98527764238894122f, -0.17096188876030122f},
    { 0.98078528040323044f, -0.19509032201612825f},
    { 0.97570213003852857f, -0.21910124015686980f},
    { 0.97003125319454397f, -0.24298017990326390f},
    { 0.96377606579543984f, -0.26671275747489837f},
    { 0.95694033573220882f, -0.29028467725446233f},
    { 0.94952818059303667f, -0.31368174039889152f},
    { 0.94154406518302081f, -0.33688985339222005f},
    { 0.93299279883473896f, -0.35989503653498817f}
};
// exp(-2*pi*i*k/32), k = 0..15
__constant__ float2 c_w32[16] = {
    { 1.00000000000000000f, -0.00000000000000000f},
    { 0.98078528040323045f, -0.19509032201612827f},
    { 0.92387953251128676f, -0.38268343236508977f},
    { 0.83146961230254524f, -0.55557023301960222f},
    { 0.70710678118654752f, -0.70710678118654752f},
    { 0.55557023301960222f, -0.83146961230254524f},
    { 0.38268343236508977f, -0.92387953251128676f},
    { 0.19509032201612827f, -0.98078528040323045f},
    { 0.00000000000000000f, -1.00000000000000000f},
    {-0.19509032201612827f, -0.98078528040323045f},
    {-0.38268343236508977f, -0.92387953251128676f},
    {-0.55557023301960222f, -0.83146961230254524f},
    {-0.70710678118654752f, -0.70710678118654752f},
    {-0.83146961230254524f, -0.55557023301960222f},
    {-0.92387953251128676f, -0.38268343236508977f},
    {-0.98078528040323045f, -0.19509032201612827f}
};

__device__ __forceinline__ float2 cmul(float2 a, float2 b) {
    return make_float2(a.x * b.x - a.y * b.y, a.x * b.y + a.y * b.x);
}
__device__ __forceinline__ float2 cadd(float2 a, float2 b) {
    return make_float2(a.x + b.x, a.y + b.y);
}
__device__ __forceinline__ float2 csub(float2 a, float2 b) {
    return make_float2(a.x - b.x, a.y - b.y);
}
__device__ __forceinline__ float2 cmul_negi(float2 a) { return make_float2(a.y, -a.x); }
__device__ __forceinline__ float2 cmul_posi(float2 a) { return make_float2(-a.y, a.x); }

// In-place forward DFT-16, natural order in/out (verified rounds 2-16).
__device__ __forceinline__ void dft16(float2 a[16]) {
    const float C1 = 0.92387953251128675613f;
    const float S1 = 0.38268343236508977173f;
    const float H  = 0.70710678118654752440f;
    const float2 W1 = make_float2( C1, -S1);
    const float2 W2 = make_float2(  H,  -H);
    const float2 W3 = make_float2( S1, -C1);
    const float2 W4 = make_float2(0.f, -1.f);
    const float2 W6 = make_float2( -H,  -H);
    const float2 W9 = make_float2(-C1,  S1);
    float2 b[16];
#pragma unroll
    for (int r1 = 0; r1 < 4; ++r1) {
        float2 x0 = a[r1], x1 = a[r1 + 4], x2 = a[r1 + 8], x3 = a[r1 + 12];
        float2 e = cadd(x0, x2), f = csub(x0, x2);
        float2 g = cadd(x1, x3), h = csub(x1, x3);
        b[r1 * 4 + 0] = cadd(e, g);
        b[r1 * 4 + 1] = cadd(f, cmul_negi(h));
        b[r1 * 4 + 2] = csub(e, g);
        b[r1 * 4 + 3] = cadd(f, cmul_posi(h));
    }
    b[5]  = cmul(b[5],  W1);
    b[6]  = cmul(b[6],  W2);
    b[7]  = cmul(b[7],  W3);
    b[9]  = cmul(b[9],  W2);
    b[10] = cmul(b[10], W4);
    b[11] = cmul(b[11], W6);
    b[13] = cmul(b[13], W3);
    b[14] = cmul(b[14], W6);
    b[15] = cmul(b[15], W9);
#pragma unroll
    for (int k1 = 0; k1 < 4; ++k1) {
        float2 x0 = b[k1], x1 = b[4 + k1], x2 = b[8 + k1], x3 = b[12 + k1];
        float2 e = cadd(x0, x2), f = csub(x0, x2);
        float2 g = cadd(x1, x3), h = csub(x1, x3);
        a[k1 + 0]  = cadd(e, g);
        a[k1 + 4]  = cadd(f, cmul_negi(h));
        a[k1 + 8]  = csub(e, g);
        a[k1 + 12] = cadd(f, cmul_posi(h));
    }
}

__device__ __forceinline__ unsigned swz(unsigned l) { return l + (l >> 8); }

// ---------------------------------------------------------------------------
// P1: radix-256, s=1, complex input (verified body, verbatim).
// ---------------------------------------------------------------------------
__global__ void __launch_bounds__(256) fft256_first(const float2* __restrict__ x,
                                                    float2* __restrict__ y) {
    __shared__ float2 sm[4112];
    unsigned tid = threadIdx.x;
    unsigned g = tid & 15u, j2 = tid >> 4;
    unsigned t = blockIdx.x * 16u + g;

    float2 a[16];
#pragma unroll
    for (int i = 0; i < 16; ++i)
        a[i] = __ldcs(&x[t + (16u * (unsigned)i + j2) * M256]);
    dft16(a);

    float sn, cs;
    __sincosf(-TWO_PI * (float)t * INVM, &sn, &cs);
    float2 wg = make_float2(cs, sn);
    float2 w1 = cmul(c_w256[j2], wg);
    float2 w = make_float2(1.f, 0.f);
#pragma unroll
    for (int k1 = 0; k1 < 16; ++k1) {
        sm[swz(tid + 256u * (unsigned)k1)] = cmul(a[k1], w);
        w = cmul(w, w1);
    }
    __syncthreads();

    unsigned k1p = tid >> 4;
#pragma unroll
    for (int j = 0; j < 16; ++j)
        a[j] = sm[swz(256u * k1p + 16u * (unsigned)j + g)];
    dft16(a);

    float2 w2 = cmul(wg, wg);
    w2 = cmul(w2, w2); w2 = cmul(w2, w2); w2 = cmul(w2, w2);  // wg^16
    float2 r[16];
    w = make_float2(1.f, 0.f);
#pragma unroll
    for (int k2 = 0; k2 < 16; ++k2) { r[k2] = cmul(a[k2], w); w = cmul(w, w2); }

    __syncthreads();
#pragma unroll
    for (int k2 = 0; k2 < 16; ++k2)
        sm[swz(256u * g + k1p + 16u * (unsigned)k2)] = r[k2];
    __syncthreads();

    unsigned base = blockIdx.x * 4096u;
#pragma unroll
    for (int i = 0; i < 16; ++i) {
        unsigned m = tid + 256u * (unsigned)i;
        __stcs(&y[base + m], sm[swz(m)]);
    }
}

// ---------------------------------------------------------------------------
// P2: radix-512 mid stage, s=256 (verified body, verbatim).
// ---------------------------------------------------------------------------
#define GS3 513u
__global__ void __launch_bounds__(512) fft512_mid(const float2* __restrict__ x,
                                                  float2* __restrict__ y) {
    extern __shared__ float2 smd[];
    const unsigned tid = threadIdx.x;
    const unsigned g = tid & 15u, u = tid >> 4;   // u in [0,32)
    const unsigned t = blockIdx.x * 16u + g;      // t in [0, 2^16)
    const unsigned gb = g * GS3;

    float2 a[16];
#pragma unroll
    for (int j = 0; j < 16; ++j)
        a[j] = __ldcs(&x[t + (u + 32u * (unsigned)j) * M512]);

    dft16(a);
    {
        float sn, cs;
        __sincosf(-TWO_PI * (float)u * (1.0f / 512.0f), &sn, &cs);
        float2 wa = make_float2(cs, sn), w = make_float2(1.f, 0.f);
#pragma unroll
        for (int k = 0; k < 16; ++k) {
            smd[gb + 16u * u + (unsigned)k] = cmul(a[k], w);
            w = cmul(w, wa);
        }
    }
    __syncthreads();

#pragma unroll
    for (int j = 0; j < 16; ++j) a[j] = smd[gb + u + 32u * (unsigned)j];
    dft16(a);
    __syncthreads();
    {
        unsigned q15 = u & 15u, p = u >> 4;
#pragma unroll
        for (int k = 0; k < 16; ++k) {
            float2 v = (p == 0u) ? a[k] : cmul(a[k], c_w32[k]);
            smd[gb + q15 + 256u * p + 16u * (unsigned)k] = v;
        }
    }
    __syncthreads();

    const unsigned q = t & 255u;
    const unsigned ps = t - q;
    const float fps = (float)ps;
    float2 Wu, W32, W256;
    { float sn, cs; __sincosf(-TWO_PI * (fps * (float)u) * INVM, &sn, &cs); Wu   = make_float2(cs, sn); }
    { float sn, cs; __sincosf(-TWO_PI * (fps * 32.0f) * INVM, &sn, &cs);    W32  = make_float2(cs, sn); }
    { float sn, cs; __sincosf(-TWO_PI * (fps * 256.0f) * INVM, &sn, &cs);   W256 = make_float2(cs, sn); }

    const unsigned base = q + (ps << 9);
    float2 w = Wu;
#pragma unroll
    for (int i = 0; i < 8; ++i) {
        unsigned t2 = u + 32u * (unsigned)i;
        float2 b0 = smd[gb + t2];
        float2 b1 = smd[gb + t2 + 256u];
        float2 v0 = cadd(b0, b1);
        float2 v1 = csub(b0, b1);
        __stcs(&y[base + (t2 << 8)],          cmul(v0, w));
        __stcs(&y[base + ((t2 + 256u) << 8)], cmul(v1, cmul(w, W256)));
        w = cmul(w, W32);
    }
}

// ---------------------------------------------------------------------------
// P3: FINAL radix-256, s=2^17, ps=0 (verified r16, verbatim).
// ---------------------------------------------------------------------------
__global__ void __launch_bounds__(256) fft256_last(const float2* __restrict__ x,
                                                   float2* __restrict__ y) {
    __shared__ float2 sm[4112];
    unsigned tid = threadIdx.x;
    unsigned g = tid & 15u, j2 = tid >> 4;
    unsigned t = blockIdx.x * 16u + g;   // t in [0, SFIN)

    float2 a[16];
#pragma unroll
    for (int i = 0; i < 16; ++i)
        a[i] = __ldcs(&x[t + (16u * (unsigned)i + j2) * SFIN]);
    dft16(a);
    {
        float2 w1 = c_w256[j2], w = make_float2(1.f, 0.f);
#pragma unroll
        for (int k1 = 0; k1 < 16; ++k1) {
            sm[swz(tid + 256u * (unsigned)k1)] = cmul(a[k1], w);
            w = cmul(w, w1);
        }
    }
    __syncthreads();

    unsigned k1p = tid >> 4;
#pragma unroll
    for (int j = 0; j < 16; ++j)
        a[j] = sm[swz(256u * k1p + 16u * (unsigned)j + g)];
    dft16(a);

    const unsigned base = t + k1p * SFIN;
#pragma unroll
    for (int k2 = 0; k2 < 16; ++k2)
        __stcs(&y[base + ((unsigned)k2 << 21)], a[k2]);  // 16*SFIN = 2^21
}

// ---------------------------------------------------------------------------
// U: Hermitian unpack with ILP-2 (two independent k per thread: v, v+M/4).
// Per-k body is the verified r7/r16 algebra verbatim.
// ---------------------------------------------------------------------------
__device__ __forceinline__ void unpack_one(const float2* __restrict__ Z,
                                           float* __restrict__ out,
                                           unsigned k, float2 Zk, float2 Zm) {
    float2 A = make_float2(0.5f * (Zk.x + Zm.x), 0.5f * (Zk.y - Zm.y));
    float2 C = make_float2(0.5f * (Zk.x - Zm.x), 0.5f * (Zk.y + Zm.y));
    float2 B = make_float2(C.y, -C.x);

    float sn, cs;
    __sincosf(-TWO_PI * (float)k * INVN, &sn, &cs);
    float2 WB = cmul(make_float2(cs, sn), B);
    float2 P = cadd(A, WB);
    float2 Q = csub(A, WB);

    __stcs(&out[k], P.x);            __stcs(&out[NFFT + k], P.y);
    __stcs(&out[MFFT - k], Q.x);     __stcs(&out[NFFT + MFFT - k], -Q.y);
    if (k != 0u) {
        __stcs(&out[NFFT - k], P.x);        __stcs(&out[2u * NFFT - k], -P.y);
        __stcs(&out[MFFT + k], Q.x);        __stcs(&out[NFFT + MFFT + k], Q.y);
    } else {
        float2 Zh = __ldcs(&Z[MHALF]);
        __stcs(&out[MHALF], Zh.x);            __stcs(&out[NFFT + MHALF], -Zh.y);
        __stcs(&out[NFFT - MHALF], Zh.x);     __stcs(&out[NFFT + NFFT - MHALF], Zh.y);
    }
}

__global__ void __launch_bounds__(256) unpack2(const float2* __restrict__ Z,
                                               float* __restrict__ out) {
    unsigned v = blockIdx.x * 256u + threadIdx.x;    // [0, 2^23)
    unsigned k0 = v;
    unsigned k1 = v + MQUART;                        // [2^23, 2^24)

    // Issue all four loads before any compute (ILP-2 latency hiding).
    float2 Zk0 = __ldcs(&Z[k0]);
    float2 Zm0 = __ldcs(&Z[(MFFT - k0) & (MFFT - 1u)]);
    float2 Zk1 = __ldcs(&Z[k1]);
    float2 Zm1 = __ldcs(&Z[MFFT - k1]);

    unpack_one(Z, out, k0, Zk0, Zm0);
    unpack_one(Z, out, k1, Zk1, Zm1);
}

// ---------------------------------------------------------------------------
// Schedule: P1: z -> D (d_out scratch); P2: D -> Blo; P3: Blo -> Bhi;
//           U: Bhi -> out (planar d_out). U never reads d_out: hazard-free.
// ---------------------------------------------------------------------------
extern "C" void kernel_launch(void* const* d_in, const int* in_sizes, int n_in,
                              void* d_out, int out_size) {
    const float2* z = (const float2*)d_in[0];   // N reals = M complex (free pack)
    float* out = (float*)d_out;
    float2* D = (float2*)d_out;                 // M float2 scratch fits in out
    float2* Bbase = nullptr;
    cudaGetSymbolAddress((void**)&Bbase, g_buf);
    float2* Blo = Bbase;
    float2* Bhi = Bbase + MFFT;

    const size_t smem2 = (size_t)(16u * GS3) * sizeof(float2);  // 65,664 B
    cudaFuncSetAttribute(fft512_mid,
                         cudaFuncAttributeMaxDynamicSharedMemorySize, (int)smem2);

    fft256_first<<<M256 / 16u, 256>>>(z, D);           // 8192 blocks
    fft512_mid  <<<M512 / 16u, 512, smem2>>>(D, Blo);  // 4096 blocks
    fft256_last <<<SFIN / 16u, 256>>>(Blo, Bhi);       // 8192 blocks
    unpack2     <<<MQUART / 256u, 256>>>(Bhi, out);    // 32768 blocks
}